// round 10
// baseline (speedup 1.0000x reference)
#include <cuda_runtime.h>
#include <math.h>
#include <stdint.h>

#define NTOK 16384
#define CDIM 8192
#define HDIM 2048
#define IDIM 8192

// ---------------------------------------------------------------------------
// Scratch (__device__ globals; allocation-free rule)
// ---------------------------------------------------------------------------
__device__ __align__(256) signed char g_qA1[(size_t)CDIM * HDIM];
__device__ __align__(256) signed char g_qA2[(size_t)CDIM * HDIM];
__device__ __align__(256) signed char g_qG1[(size_t)IDIM * HDIM];
__device__ __align__(256) signed char g_qG2[(size_t)IDIM * HDIM];
__device__ __align__(256) signed char g_qU1[(size_t)IDIM * HDIM];
__device__ __align__(256) signed char g_qU2[(size_t)IDIM * HDIM];
__device__ __align__(256) signed char g_qD1[(size_t)HDIM * IDIM];
__device__ __align__(256) signed char g_qD2[(size_t)HDIM * IDIM];
__device__ __align__(256) signed char g_qH1[(size_t)CDIM * IDIM];
__device__ __align__(256) signed char g_qH2[(size_t)CDIM * IDIM];
__device__ float g_sA[CDIM];
__device__ float g_sG[IDIM];
__device__ float g_sU[IDIM];
__device__ float g_sD[HDIM];
__device__ float g_sH[CDIM];
__device__ __align__(256) float g_h[(size_t)CDIM * IDIM];      // silu(g)*u fp32
__device__ __align__(256) float g_down[(size_t)CDIM * HDIM];

// ---------------------------------------------------------------------------
// helpers
// ---------------------------------------------------------------------------
__device__ __forceinline__ uint32_t smem_u32(const void* p) {
    return (uint32_t)__cvta_generic_to_shared(p);
}
__device__ __forceinline__ void ldsm4(uint32_t a, uint32_t& r0, uint32_t& r1,
                                      uint32_t& r2, uint32_t& r3) {
    asm volatile("ldmatrix.sync.aligned.m8n8.x4.shared.b16 {%0,%1,%2,%3}, [%4];"
                 : "=r"(r0), "=r"(r1), "=r"(r2), "=r"(r3) : "r"(a));
}
// s8 MMA: D(s32) += A(16x32 s8) * B(32x8 s8)
__device__ __forceinline__ void imma(int* d, const uint32_t* a,
                                     uint32_t b0, uint32_t b1) {
    asm volatile(
        "mma.sync.aligned.m16n8k32.row.col.s32.s8.s8.s32 "
        "{%0,%1,%2,%3},{%4,%5,%6,%7},{%8,%9},{%0,%1,%2,%3};"
        : "+r"(d[0]), "+r"(d[1]), "+r"(d[2]), "+r"(d[3])
        : "r"(a[0]), "r"(a[1]), "r"(a[2]), "r"(a[3]), "r"(b0), "r"(b1));
}
__device__ __forceinline__ float silu(float g) { return g / (1.f + __expf(-g)); }

#define INV254 0.003937007874015748f

// smem rows: 64 int8 padded to 80B (5x16B) — same conflict-free geometry as R3
#define ROWB 80
// k1 planes: A1 A2 (128 rows) | G1 G2 U1 U2 (64 rows)
#define P1_A2  10240
#define P1_G1  20480
#define P1_G2  25600
#define P1_U1  30720
#define P1_U2  35840
#define STAGE1 40960
#define SMEM1  (2 * STAGE1)   // 80 KB
// k2 planes: H1 H2 D1 D2 (128 rows each)
#define P2_H2  10240
#define P2_D1  20480
#define P2_D2  30720
#define STAGE2 40960
#define SMEM2  (2 * STAGE2)

#define NC1 (HDIM / 64)   // 32 chunks
#define NC2 (IDIM / 64)   // 128 chunks

// ---------------------------------------------------------------------------
// pre-pass: per-row 15-bit quantization  v = s*(q1 + q2/254)
// ---------------------------------------------------------------------------
__global__ __launch_bounds__(256)
void quant_rows(const float* __restrict__ src, signed char* __restrict__ q1,
                signed char* __restrict__ q2, float* __restrict__ scale,
                int rowlen, const int* __restrict__ gather)
{
    const int row = blockIdx.x;
    const int srow = gather ? __ldg(gather + row) : row;
    const float4* r = reinterpret_cast<const float4*>(src + (size_t)srow * rowlen);
    const int n4 = rowlen >> 2;
    float m = 0.f;
    for (int i = threadIdx.x; i < n4; i += 256) {
        float4 v = r[i];
        m = fmaxf(m, fmaxf(fmaxf(fabsf(v.x), fabsf(v.y)),
                           fmaxf(fabsf(v.z), fabsf(v.w))));
    }
    __shared__ float red[256];
    red[threadIdx.x] = m;
    __syncthreads();
    for (int o = 128; o > 0; o >>= 1) {
        if (threadIdx.x < o)
            red[threadIdx.x] = fmaxf(red[threadIdx.x], red[threadIdx.x + o]);
        __syncthreads();
    }
    const float s = (red[0] > 0.f) ? red[0] / 127.f : 1.f;
    const float inv = 1.f / s;
    if (threadIdx.x == 0) scale[row] = s;
    char4* o1 = reinterpret_cast<char4*>(q1 + (size_t)row * rowlen);
    char4* o2 = reinterpret_cast<char4*>(q2 + (size_t)row * rowlen);
    for (int i = threadIdx.x; i < n4; i += 256) {
        float4 v = r[i];
        float t; int a; int b;
        char4 c1, c2;
        t = v.x * inv; a = __float2int_rn(t); a = max(-127, min(127, a));
        b = __float2int_rn((t - (float)a) * 254.f); b = max(-127, min(127, b));
        c1.x = (signed char)a; c2.x = (signed char)b;
        t = v.y * inv; a = __float2int_rn(t); a = max(-127, min(127, a));
        b = __float2int_rn((t - (float)a) * 254.f); b = max(-127, min(127, b));
        c1.y = (signed char)a; c2.y = (signed char)b;
        t = v.z * inv; a = __float2int_rn(t); a = max(-127, min(127, a));
        b = __float2int_rn((t - (float)a) * 254.f); b = max(-127, min(127, b));
        c1.z = (signed char)a; c2.z = (signed char)b;
        t = v.w * inv; a = __float2int_rn(t); a = max(-127, min(127, a));
        b = __float2int_rn((t - (float)a) * 254.f); b = max(-127, min(127, b));
        c1.w = (signed char)a; c2.w = (signed char)b;
        o1[i] = c1; o2[i] = c2;
    }
}

// ---------------------------------------------------------------------------
// Kernel 1: dual int8 GEMM (gate,up) + SiLU epilogue.
// CTA 128m x 64n of gate AND up. 8 warps: 0-3 gate (R=32w), 4-7 up.
// Warp tile 32x64; D1/D2 int accumulators (64+64 regs).
// ---------------------------------------------------------------------------
__global__ __launch_bounds__(256, 1)
void k1_gateup()
{
    extern __shared__ __align__(128) char sm[];
    const uint32_t smb = smem_u32(sm);
    const int tid  = threadIdx.x;
    const int wid  = tid >> 5;
    const int lane = tid & 31;
    const int m0 = blockIdx.x * 128;   // m fastest
    const int n0 = blockIdx.y * 64;

    // staging: A rows 128 (2 thr/row, 2x16B per plane), B rows 64 (4 thr/row, 1x16B)
    const int arow = tid >> 1;
    const int aq   = (tid & 1) * 32;
    const size_t aOff = (size_t)(m0 + arow) * HDIM + aq;
    const int stsA = arow * ROWB + aq;
    const int brow = tid >> 2;
    const int bq   = (tid & 3) * 16;
    const size_t bOff = (size_t)(n0 + brow) * HDIM + bq;
    const int stsB = brow * ROWB + bq;

    // ldmatrix lane geometry (R3)
    const int laneRow = ((lane >> 3) & 1) * 8 + (lane & 7);
    const int laneK   = (lane >> 4) * 16;
    const int R       = 32 * (wid & 3);
    const int b1Sec   = (wid >= 4) ? P1_U1 : P1_G1;   // plane2 = +5120

    int acc1[2][8][4], acc2[2][8][4];
#pragma unroll
    for (int f = 0; f < 2; f++)
#pragma unroll
        for (int n = 0; n < 8; n++)
#pragma unroll
            for (int q = 0; q < 4; q++) { acc1[f][n][q] = 0; acc2[f][n][q] = 0; }

    // prologue: chunk 0
    uint4 vA1a, vA1b, vA2a, vA2b, vG1, vG2, vU1, vU2;
    vA1a = *reinterpret_cast<const uint4*>(g_qA1 + aOff);
    vA1b = *reinterpret_cast<const uint4*>(g_qA1 + aOff + 16);
    vA2a = *reinterpret_cast<const uint4*>(g_qA2 + aOff);
    vA2b = *reinterpret_cast<const uint4*>(g_qA2 + aOff + 16);
    vG1  = *reinterpret_cast<const uint4*>(g_qG1 + bOff);
    vG2  = *reinterpret_cast<const uint4*>(g_qG2 + bOff);
    vU1  = *reinterpret_cast<const uint4*>(g_qU1 + bOff);
    vU2  = *reinterpret_cast<const uint4*>(g_qU2 + bOff);
    {
        char* st = sm;
        *reinterpret_cast<uint4*>(st + stsA)               = vA1a;
        *reinterpret_cast<uint4*>(st + stsA + 16)          = vA1b;
        *reinterpret_cast<uint4*>(st + P1_A2 + stsA)       = vA2a;
        *reinterpret_cast<uint4*>(st + P1_A2 + stsA + 16)  = vA2b;
        *reinterpret_cast<uint4*>(st + P1_G1 + stsB)       = vG1;
        *reinterpret_cast<uint4*>(st + P1_G2 + stsB)       = vG2;
        *reinterpret_cast<uint4*>(st + P1_U1 + stsB)       = vU1;
        *reinterpret_cast<uint4*>(st + P1_U2 + stsB)       = vU2;
    }

#pragma unroll 1
    for (int c = 0; c < NC1; c++) {
        __syncthreads();
        if (c + 1 < NC1) {
            const int k0 = (c + 1) * 64;
            vA1a = *reinterpret_cast<const uint4*>(g_qA1 + aOff + k0);
            vA1b = *reinterpret_cast<const uint4*>(g_qA1 + aOff + k0 + 16);
            vA2a = *reinterpret_cast<const uint4*>(g_qA2 + aOff + k0);
            vA2b = *reinterpret_cast<const uint4*>(g_qA2 + aOff + k0 + 16);
            vG1  = *reinterpret_cast<const uint4*>(g_qG1 + bOff + k0);
            vG2  = *reinterpret_cast<const uint4*>(g_qG2 + bOff + k0);
            vU1  = *reinterpret_cast<const uint4*>(g_qU1 + bOff + k0);
            vU2  = *reinterpret_cast<const uint4*>(g_qU2 + bOff + k0);
        }
        const uint32_t sb = smb + (uint32_t)(c & 1) * STAGE1;
#pragma unroll
        for (int s = 0; s < 2; s++) {
            const uint32_t ab = sb + (uint32_t)((R + laneRow) * ROWB + laneK + 32 * s);
            uint32_t ah[2][4], al[2][4];
            ldsm4(ab,                      ah[0][0], ah[0][1], ah[0][2], ah[0][3]);
            ldsm4(ab + 16 * ROWB,          ah[1][0], ah[1][1], ah[1][2], ah[1][3]);
            ldsm4(ab + P1_A2,              al[0][0], al[0][1], al[0][2], al[0][3]);
            ldsm4(ab + P1_A2 + 16 * ROWB,  al[1][0], al[1][1], al[1][2], al[1][3]);
#pragma unroll
            for (int gp = 0; gp < 4; gp++) {
                const uint32_t bb = sb + (uint32_t)(b1Sec +
                    (16 * gp + laneRow) * ROWB + laneK + 32 * s);
                uint32_t b1[4], b2[4];
                ldsm4(bb,        b1[0], b1[1], b1[2], b1[3]);
                ldsm4(bb + 5120, b2[0], b2[1], b2[2], b2[3]);
#pragma unroll
                for (int f = 0; f < 2; f++)
#pragma unroll
                    for (int h = 0; h < 2; h++) {
                        imma(acc1[f][2 * gp + h], ah[f], b1[h], b1[2 + h]);
                        imma(acc2[f][2 * gp + h], ah[f], b2[h], b2[2 + h]);
                        imma(acc2[f][2 * gp + h], al[f], b1[h], b1[2 + h]);
                    }
            }
        }
        if (c + 1 < NC1) {
            char* nb = sm + (size_t)((c + 1) & 1) * STAGE1;
            *reinterpret_cast<uint4*>(nb + stsA)              = vA1a;
            *reinterpret_cast<uint4*>(nb + stsA + 16)         = vA1b;
            *reinterpret_cast<uint4*>(nb + P1_A2 + stsA)      = vA2a;
            *reinterpret_cast<uint4*>(nb + P1_A2 + stsA + 16) = vA2b;
            *reinterpret_cast<uint4*>(nb + P1_G1 + stsB)      = vG1;
            *reinterpret_cast<uint4*>(nb + P1_G2 + stsB)      = vG2;
            *reinterpret_cast<uint4*>(nb + P1_U1 + stsB)      = vU1;
            *reinterpret_cast<uint4*>(nb + P1_U2 + stsB)      = vU2;
        }
    }

    // ---- epilogue: up warps dequant + park; gate warps dequant + combine ----
    __syncthreads();
    float* upbuf = reinterpret_cast<float*>(sm);   // 4 warps x 32 x 68 floats
    if (wid >= 4) {
        const int w = wid - 4;
#pragma unroll
        for (int f = 0; f < 2; f++)
#pragma unroll
            for (int n = 0; n < 8; n++) {
                int lr = 16 * f + (lane >> 2);
                int lc = 8 * n + (lane & 3) * 2;
                float sa0 = __ldg(&g_sA[m0 + R + lr]);
                float sa1 = __ldg(&g_sA[m0 + R + lr + 8]);
                float su0 = __ldg(&g_sU[n0 + lc]);
                float su1 = __ldg(&g_sU[n0 + lc + 1]);
                const int* c1 = acc1[f][n];
                const int* c2 = acc2[f][n];
                float* b0 = upbuf + w * 2176 + lr * 68 + lc;
                b0[0] = sa0 * su0 * ((float)c1[0] + (float)c2[0] * INV254);
                b0[1] = sa0 * su1 * ((float)c1[1] + (float)c2[1] * INV254);
                float* b1 = b0 + 8 * 68;
                b1[0] = sa1 * su0 * ((float)c1[2] + (float)c2[2] * INV254);
                b1[1] = sa1 * su1 * ((float)c1[3] + (float)c2[3] * INV254);
            }
    }
    __syncthreads();
    if (wid < 4) {
        const int w = wid;
#pragma unroll
        for (int f = 0; f < 2; f++)
#pragma unroll
            for (int n = 0; n < 8; n++) {
                int lr = 16 * f + (lane >> 2);
                int lc = 8 * n + (lane & 3) * 2;
                float sa0 = __ldg(&g_sA[m0 + R + lr]);
                float sa1 = __ldg(&g_sA[m0 + R + lr + 8]);
                float sg0 = __ldg(&g_sG[n0 + lc]);
                float sg1 = __ldg(&g_sG[n0 + lc + 1]);
                const int* c1 = acc1[f][n];
                const int* c2 = acc2[f][n];
                float g00 = sa0 * sg0 * ((float)c1[0] + (float)c2[0] * INV254);
                float g01 = sa0 * sg1 * ((float)c1[1] + (float)c2[1] * INV254);
                float g10 = sa1 * sg0 * ((float)c1[2] + (float)c2[2] * INV254);
                float g11 = sa1 * sg1 * ((float)c1[3] + (float)c2[3] * INV254);
                const float* b0 = upbuf + w * 2176 + lr * 68 + lc;
                const float* b1 = b0 + 8 * 68;
                float* o0 = g_h + (size_t)(m0 + R + lr) * IDIM + n0 + lc;
                float* o1 = o0 + (size_t)8 * IDIM;
                *reinterpret_cast<float2*>(o0) =
                    make_float2(silu(g00) * b0[0], silu(g01) * b0[1]);
                *reinterpret_cast<float2*>(o1) =
                    make_float2(silu(g10) * b1[0], silu(g11) * b1[1]);
            }
    }
}

// ---------------------------------------------------------------------------
// Kernel 2: int8 down projection. CTA 128m x 128n; 8 warps 4m x 2n; warp 32x64.
// ---------------------------------------------------------------------------
__global__ __launch_bounds__(256, 1)
void k2_down()
{
    extern __shared__ __align__(128) char sm[];
    const uint32_t smb = smem_u32(sm);
    const int tid  = threadIdx.x;
    const int wid  = tid >> 5;
    const int lane = tid & 31;
    const int m0 = blockIdx.x * 128;
    const int n0 = blockIdx.y * 128;

    // staging: all planes 128 rows, 2 thr/row, 2x16B per plane... A 2 planes, B 2 planes
    const int prow = tid >> 1;
    const int pq   = (tid & 1) * 32;
    const size_t aOff = (size_t)(m0 + prow) * IDIM + pq;
    const size_t bOff = (size_t)(n0 + prow) * IDIM + pq;
    const int sts = prow * ROWB + pq;

    const int laneRow = ((lane >> 3) & 1) * 8 + (lane & 7);
    const int laneK   = (lane >> 4) * 16;
    const int R       = 32 * (wid & 3);
    const int Cw      = 64 * (wid >> 2);

    int acc1[2][8][4], acc2[2][8][4];
#pragma unroll
    for (int f = 0; f < 2; f++)
#pragma unroll
        for (int n = 0; n < 8; n++)
#pragma unroll
            for (int q = 0; q < 4; q++) { acc1[f][n][q] = 0; acc2[f][n][q] = 0; }

    uint4 vH1a, vH1b, vH2a, vH2b, vD1a, vD1b, vD2a, vD2b;
    vH1a = *reinterpret_cast<const uint4*>(g_qH1 + aOff);
    vH1b = *reinterpret_cast<const uint4*>(g_qH1 + aOff + 16);
    vH2a = *reinterpret_cast<const uint4*>(g_qH2 + aOff);
    vH2b = *reinterpret_cast<const uint4*>(g_qH2 + aOff + 16);
    vD1a = *reinterpret_cast<const uint4*>(g_qD1 + bOff);
    vD1b = *reinterpret_cast<const uint4*>(g_qD1 + bOff + 16);
    vD2a = *reinterpret_cast<const uint4*>(g_qD2 + bOff);
    vD2b = *reinterpret_cast<const uint4*>(g_qD2 + bOff + 16);
    {
        char* st = sm;
        *reinterpret_cast<uint4*>(st + sts)              = vH1a;
        *reinterpret_cast<uint4*>(st + sts + 16)         = vH1b;
        *reinterpret_cast<uint4*>(st + P2_H2 + sts)      = vH2a;
        *reinterpret_cast<uint4*>(st + P2_H2 + sts + 16) = vH2b;
        *reinterpret_cast<uint4*>(st + P2_D1 + sts)      = vD1a;
        *reinterpret_cast<uint4*>(st + P2_D1 + sts + 16) = vD1b;
        *reinterpret_cast<uint4*>(st + P2_D2 + sts)      = vD2a;
        *reinterpret_cast<uint4*>(st + P2_D2 + sts + 16) = vD2b;
    }

#pragma unroll 1
    for (int c = 0; c < NC2; c++) {
        __syncthreads();
        if (c + 1 < NC2) {
            const int k0 = (c + 1) * 64;
            vH1a = *reinterpret_cast<const uint4*>(g_qH1 + aOff + k0);
            vH1b = *reinterpret_cast<const uint4*>(g_qH1 + aOff + k0 + 16);
            vH2a = *reinterpret_cast<const uint4*>(g_qH2 + aOff + k0);
            vH2b = *reinterpret_cast<const uint4*>(g_qH2 + aOff + k0 + 16);
            vD1a = *reinterpret_cast<const uint4*>(g_qD1 + bOff + k0);
            vD1b = *reinterpret_cast<const uint4*>(g_qD1 + bOff + k0 + 16);
            vD2a = *reinterpret_cast<const uint4*>(g_qD2 + bOff + k0);
            vD2b = *reinterpret_cast<const uint4*>(g_qD2 + bOff + k0 + 16);
        }
        const uint32_t sb = smb + (uint32_t)(c & 1) * STAGE2;
#pragma unroll
        for (int s = 0; s < 2; s++) {
            const uint32_t ab = sb + (uint32_t)((R + laneRow) * ROWB + laneK + 32 * s);
            uint32_t ah[2][4], al[2][4];
            ldsm4(ab,                      ah[0][0], ah[0][1], ah[0][2], ah[0][3]);
            ldsm4(ab + 16 * ROWB,          ah[1][0], ah[1][1], ah[1][2], ah[1][3]);
            ldsm4(ab + P2_H2,              al[0][0], al[0][1], al[0][2], al[0][3]);
            ldsm4(ab + P2_H2 + 16 * ROWB,  al[1][0], al[1][1], al[1][2], al[1][3]);
#pragma unroll
            for (int gp = 0; gp < 4; gp++) {
                const uint32_t bb = sb + (uint32_t)(P2_D1 +
                    (Cw + 16 * gp + laneRow) * ROWB + laneK + 32 * s);
                uint32_t b1[4], b2[4];
                ldsm4(bb,         b1[0], b1[1], b1[2], b1[3]);
                ldsm4(bb + 10240, b2[0], b2[1], b2[2], b2[3]);
#pragma unroll
                for (int f = 0; f < 2; f++)
#pragma unroll
                    for (int h = 0; h < 2; h++) {
                        imma(acc1[f][2 * gp + h], ah[f], b1[h], b1[2 + h]);
                        imma(acc2[f][2 * gp + h], ah[f], b2[h], b2[2 + h]);
                        imma(acc2[f][2 * gp + h], al[f], b1[h], b1[2 + h]);
                    }
            }
        }
        if (c + 1 < NC2) {
            char* nb = sm + (size_t)((c + 1) & 1) * STAGE2;
            *reinterpret_cast<uint4*>(nb + sts)              = vH1a;
            *reinterpret_cast<uint4*>(nb + sts + 16)         = vH1b;
            *reinterpret_cast<uint4*>(nb + P2_H2 + sts)      = vH2a;
            *reinterpret_cast<uint4*>(nb + P2_H2 + sts + 16) = vH2b;
            *reinterpret_cast<uint4*>(nb + P2_D1 + sts)      = vD1a;
            *reinterpret_cast<uint4*>(nb + P2_D1 + sts + 16) = vD1b;
            *reinterpret_cast<uint4*>(nb + P2_D2 + sts)      = vD2a;
            *reinterpret_cast<uint4*>(nb + P2_D2 + sts + 16) = vD2b;
        }
    }

    // epilogue: dequant + direct fp32 stores
#pragma unroll
    for (int f = 0; f < 2; f++)
#pragma unroll
        for (int n = 0; n < 8; n++) {
            int r  = m0 + R + 16 * f + (lane >> 2);
            int cc = n0 + Cw + 8 * n + (lane & 3) * 2;
            float sh0 = __ldg(&g_sH[r]);
            float sh1 = __ldg(&g_sH[r + 8]);
            float sd0 = __ldg(&g_sD[cc]);
            float sd1 = __ldg(&g_sD[cc + 1]);
            const int* c1 = acc1[f][n];
            const int* c2 = acc2[f][n];
            float* o0 = g_down + (size_t)r * HDIM + cc;
            float* o1 = o0 + (size_t)8 * HDIM;
            *reinterpret_cast<float2*>(o0) = make_float2(
                sh0 * sd0 * ((float)c1[0] + (float)c2[0] * INV254),
                sh0 * sd1 * ((float)c1[1] + (float)c2[1] * INV254));
            *reinterpret_cast<float2*>(o1) = make_float2(
                sh1 * sd0 * ((float)c1[2] + (float)c2[2] * INV254),
                sh1 * sd1 * ((float)c1[3] + (float)c2[3] * INV254));
        }
}

// ---------------------------------------------------------------------------
// Kernel 3: scatter
// ---------------------------------------------------------------------------
__global__ __launch_bounds__(256)
void scatter_kernel(const int* __restrict__ scatter_indices,
                    float* __restrict__ out)
{
    const int t = blockIdx.x;
    const int c = scatter_indices[t];
    const float4* src = reinterpret_cast<const float4*>(g_down + (size_t)c * HDIM);
    float4*       dst = reinterpret_cast<float4*>(out + (size_t)t * HDIM);
#pragma unroll
    for (int j = threadIdx.x; j < HDIM / 4; j += 256)
        dst[j] = src[j];
}

// ---------------------------------------------------------------------------
extern "C" void kernel_launch(void* const* d_in, const int* in_sizes, int n_in,
                              void* d_out, int out_size)
{
    const float* x  = (const float*)d_in[0];
    const float* Wg = (const float*)d_in[1];
    const float* Wu = (const float*)d_in[2];
    const float* Wd = (const float*)d_in[3];
    const int*   fg = (const int*)d_in[4];
    const int*   sc = (const int*)d_in[5];
    float*       out = (float*)d_out;

    cudaFuncSetAttribute(k1_gateup, cudaFuncAttributeMaxDynamicSharedMemorySize, SMEM1);
    cudaFuncSetAttribute(k2_down,   cudaFuncAttributeMaxDynamicSharedMemorySize, SMEM2);

    signed char *qA1, *qA2, *qG1, *qG2, *qU1, *qU2, *qD1, *qD2, *qH1, *qH2;
    float *sA, *sG, *sU, *sD, *sH, *gh;
    cudaGetSymbolAddress((void**)&qA1, g_qA1);
    cudaGetSymbolAddress((void**)&qA2, g_qA2);
    cudaGetSymbolAddress((void**)&qG1, g_qG1);
    cudaGetSymbolAddress((void**)&qG2, g_qG2);
    cudaGetSymbolAddress((void**)&qU1, g_qU1);
    cudaGetSymbolAddress((void**)&qU2, g_qU2);
    cudaGetSymbolAddress((void**)&qD1, g_qD1);
    cudaGetSymbolAddress((void**)&qD2, g_qD2);
    cudaGetSymbolAddress((void**)&qH1, g_qH1);
    cudaGetSymbolAddress((void**)&qH2, g_qH2);
    cudaGetSymbolAddress((void**)&sA, g_sA);
    cudaGetSymbolAddress((void**)&sG, g_sG);
    cudaGetSymbolAddress((void**)&sU, g_sU);
    cudaGetSymbolAddress((void**)&sD, g_sD);
    cudaGetSymbolAddress((void**)&sH, g_sH);
    cudaGetSymbolAddress((void**)&gh, g_h);

    // quantization pre-passes
    quant_rows<<<CDIM, 256>>>(x,  qA1, qA2, sA, HDIM, fg);       // gather + quant
    quant_rows<<<IDIM, 256>>>(Wg, qG1, qG2, sG, HDIM, nullptr);
    quant_rows<<<IDIM, 256>>>(Wu, qU1, qU2, sU, HDIM, nullptr);
    quant_rows<<<HDIM, 256>>>(Wd, qD1, qD2, sD, IDIM, nullptr);

    dim3 g1(CDIM / 128, IDIM / 64);    // (64 m fastest, 128 n)
    k1_gateup<<<g1, 256, SMEM1>>>();

    quant_rows<<<CDIM, 256>>>(gh, qH1, qH2, sH, IDIM, nullptr);  // quant g_h rows

    dim3 g2(CDIM / 128, HDIM / 128);   // (64 m fastest, 16 n)
    k2_down<<<g2, 256, SMEM2>>>();

    scatter_kernel<<<NTOK, 256>>>(sc, out);
}

// round 11
// speedup vs baseline: 2.3966x; 2.3966x over previous
#include <cuda_runtime.h>
#include <cuda_bf16.h>
#include <math.h>
#include <stdint.h>

#define NTOK 16384
#define CDIM 8192
#define HDIM 2048
#define IDIM 8192

// Scratch (allocation-free rule: __device__ globals)
__device__ __align__(256) float g_h[(size_t)CDIM * IDIM];      // silu(g)*u
__device__ __align__(256) float g_down[(size_t)CDIM * HDIM];

// ---------------------------------------------------------------------------
// helpers (plain sm_80-era PTX only)
// ---------------------------------------------------------------------------
__device__ __forceinline__ uint32_t smem_u32(const void* p) {
    return (uint32_t)__cvta_generic_to_shared(p);
}
__device__ __forceinline__ void ldsm4(uint32_t a, uint32_t& r0, uint32_t& r1,
                                      uint32_t& r2, uint32_t& r3) {
    asm volatile("ldmatrix.sync.aligned.m8n8.x4.shared.b16 {%0,%1,%2,%3}, [%4];"
                 : "=r"(r0), "=r"(r1), "=r"(r2), "=r"(r3) : "r"(a));
}
__device__ __forceinline__ void hmma(float* c, const uint32_t* a,
                                     uint32_t b0, uint32_t b1) {
    asm volatile(
        "mma.sync.aligned.m16n8k16.row.col.f32.bf16.bf16.f32 "
        "{%0,%1,%2,%3},{%4,%5,%6,%7},{%8,%9},{%0,%1,%2,%3};"
        : "+f"(c[0]), "+f"(c[1]), "+f"(c[2]), "+f"(c[3])
        : "r"(a[0]), "r"(a[1]), "r"(a[2]), "r"(a[3]), "r"(b0), "r"(b1));
}
// fp32 -> (hi, lo) bf16 split of 4 consecutive K elements; 8B packed stores
__device__ __forceinline__ void split_store(char* hi, char* lo, float4 v) {
    __nv_bfloat162 h0 = __floats2bfloat162_rn(v.x, v.y);
    __nv_bfloat162 h1 = __floats2bfloat162_rn(v.z, v.w);
    float2 f0 = __bfloat1622float2(h0);
    float2 f1 = __bfloat1622float2(h1);
    __nv_bfloat162 l0 = __floats2bfloat162_rn(v.x - f0.x, v.y - f0.y);
    __nv_bfloat162 l1 = __floats2bfloat162_rn(v.z - f1.x, v.w - f1.y);
    uint32_t h0u = *reinterpret_cast<uint32_t*>(&h0);
    uint32_t h1u = *reinterpret_cast<uint32_t*>(&h1);
    uint32_t l0u = *reinterpret_cast<uint32_t*>(&l0);
    uint32_t l1u = *reinterpret_cast<uint32_t*>(&l1);
    *reinterpret_cast<uint2*>(hi) = make_uint2(h0u, h1u);
    *reinterpret_cast<uint2*>(lo) = make_uint2(l0u, l1u);
}
__device__ __forceinline__ float silu(float g) { return g / (1.f + __expf(-g)); }

// smem rows: 32 bf16 padded to 40 (80B = 5x16B) — conflict-free ldmatrix
#define ROWB 80
// k1 planes: A_hi(128r) A_lo | G_hi(64r) G_lo | U_hi U_lo
#define K1_ALO   10240
#define K1_GHI   20480
#define K1_GLO   25600
#define K1_UHI   30720
#define K1_ULO   35840
#define STAGE1   40960
#define SMEM1    (2 * STAGE1)   // 80 KB -> 2 CTAs/SM
// k2 planes: A_hi(128r) A_lo | B_hi(128r) B_lo
#define K2_ALO   10240
#define K2_BHI   20480
#define K2_BLO   30720
#define STAGE2   40960
#define SMEM2    (2 * STAGE2)   // 80 KB -> 2 CTAs/SM

#define NC1 (HDIM / 32)   // 64 chunks
#define NC2 (IDIM / 32)   // 256 chunks

// ---------------------------------------------------------------------------
// Kernel 1: gather + dual GEMM (gate,up) + SiLU. CTA 128m x 64n, 2 CTAs/SM.
// Warps 0-3 gate (32m x 64n each), warps 4-7 up. Serial staging after MMA;
// latency hidden by the co-resident CTA.
// ---------------------------------------------------------------------------
__global__ __launch_bounds__(256, 2)
void k1_gateup(const float* __restrict__ x,
               const float* __restrict__ Wg,
               const float* __restrict__ Wu,
               const int* __restrict__ fg)
{
    extern __shared__ __align__(128) char sm[];
    const uint32_t smb = smem_u32(sm);
    const int tid  = threadIdx.x;
    const int wid  = tid >> 5;
    const int lane = tid & 31;
    const int m0 = blockIdx.x * 128;   // m fastest -> B tiles L2-resident
    const int n0 = blockIdx.y * 64;

    // A staging (R3 geometry): 8 threads/row, one float4 each, 4 rows/thread
    const int rbase = tid >> 3;
    const int c4    = (tid & 7) * 4;
    const float* pA[4];
    int stsA[4];
#pragma unroll
    for (int j = 0; j < 4; j++) {
        int row = rbase + 32 * j;
        pA[j] = x + (size_t)__ldg(fg + m0 + row) * HDIM + c4;
        stsA[j] = row * ROWB + (tid & 7) * 8;
    }
    // B staging: 64 rows, 4 threads/row, 2 float4 each (segments 2q, 2q+1)
    const int brow = tid >> 2;
    const int bq   = (tid & 3) * 2;
    const float* pG = Wg + (size_t)(n0 + brow) * HDIM + bq * 4;
    const float* pU = Wu + (size_t)(n0 + brow) * HDIM + bq * 4;
    const int stsB = brow * ROWB + bq * 8;

    // ldmatrix lane geometry (R3)
    const int laneRow = ((lane >> 3) & 1) * 8 + (lane & 7);
    const int laneK   = (lane >> 4) * 16;
    const int R       = 32 * (wid & 3);
    const int bSec    = (wid >= 4) ? K1_UHI : K1_GHI;   // lo plane = +5120

    float acc[2][8][4];
#pragma unroll
    for (int f = 0; f < 2; f++)
#pragma unroll
        for (int n = 0; n < 8; n++)
#pragma unroll
            for (int q = 0; q < 4; q++) acc[f][n][q] = 0.f;

#define K1_STAGE(DST, K0) do {                                                 \
    char* st = (DST);                                                          \
    float4 a0 = *reinterpret_cast<const float4*>(pA[0] + (K0));                \
    float4 a1 = *reinterpret_cast<const float4*>(pA[1] + (K0));                \
    float4 a2 = *reinterpret_cast<const float4*>(pA[2] + (K0));                \
    float4 a3 = *reinterpret_cast<const float4*>(pA[3] + (K0));                \
    float4 gg0 = *reinterpret_cast<const float4*>(pG + (K0));                  \
    float4 gg1 = *reinterpret_cast<const float4*>(pG + (K0) + 4);              \
    float4 uu0 = *reinterpret_cast<const float4*>(pU + (K0));                  \
    float4 uu1 = *reinterpret_cast<const float4*>(pU + (K0) + 4);              \
    split_store(st + stsA[0], st + K1_ALO + stsA[0], a0);                      \
    split_store(st + stsA[1], st + K1_ALO + stsA[1], a1);                      \
    split_store(st + stsA[2], st + K1_ALO + stsA[2], a2);                      \
    split_store(st + stsA[3], st + K1_ALO + stsA[3], a3);                      \
    split_store(st + K1_GHI + stsB,     st + K1_GLO + stsB,     gg0);          \
    split_store(st + K1_GHI + stsB + 8, st + K1_GLO + stsB + 8, gg1);          \
    split_store(st + K1_UHI + stsB,     st + K1_ULO + stsB,     uu0);          \
    split_store(st + K1_UHI + stsB + 8, st + K1_ULO + stsB + 8, uu1);          \
} while (0)

    K1_STAGE(sm, 0);

#pragma unroll 1
    for (int c = 0; c < NC1; c++) {
        __syncthreads();
        const uint32_t sb = smb + (uint32_t)(c & 1) * STAGE1;
#pragma unroll
        for (int s = 0; s < 2; s++) {
            const uint32_t ab = sb + (uint32_t)((R + laneRow) * ROWB + laneK + 32 * s);
            uint32_t ah[2][4], al[2][4];
            ldsm4(ab,                      ah[0][0], ah[0][1], ah[0][2], ah[0][3]);
            ldsm4(ab + 16 * ROWB,          ah[1][0], ah[1][1], ah[1][2], ah[1][3]);
            ldsm4(ab + K1_ALO,             al[0][0], al[0][1], al[0][2], al[0][3]);
            ldsm4(ab + K1_ALO + 16 * ROWB, al[1][0], al[1][1], al[1][2], al[1][3]);
#pragma unroll
            for (int gp = 0; gp < 4; gp++) {
                const uint32_t bb = sb + (uint32_t)(bSec +
                    (16 * gp + laneRow) * ROWB + laneK + 32 * s);
                uint32_t bh[4], bl[4];
                ldsm4(bb,        bh[0], bh[1], bh[2], bh[3]);
                ldsm4(bb + 5120, bl[0], bl[1], bl[2], bl[3]);
#pragma unroll
                for (int f = 0; f < 2; f++)
#pragma unroll
                    for (int h = 0; h < 2; h++) {
                        float* cc = acc[f][2 * gp + h];
                        hmma(cc, ah[f], bh[h], bh[2 + h]);
                        hmma(cc, ah[f], bl[h], bl[2 + h]);
                        hmma(cc, al[f], bh[h], bh[2 + h]);
                    }
            }
        }
        if (c + 1 < NC1)
            K1_STAGE(sm + (size_t)((c + 1) & 1) * STAGE1, (c + 1) * 32);
    }
#undef K1_STAGE

    // ---- epilogue: up warps park 32x64 tiles in smem; gate warps combine ----
    __syncthreads();
    float* upbuf = reinterpret_cast<float*>(sm);   // 4 x (32 x 68) floats
    if (wid >= 4) {
        float* base = upbuf + (wid - 4) * 2176;
#pragma unroll
        for (int f = 0; f < 2; f++)
#pragma unroll
            for (int n = 0; n < 8; n++) {
                int row = 16 * f + (lane >> 2);
                int col = 8 * n + (lane & 3) * 2;
                float* b0 = base + row * 68 + col;
                b0[0] = acc[f][n][0]; b0[1] = acc[f][n][1];
                float* b1 = b0 + 8 * 68;
                b1[0] = acc[f][n][2]; b1[1] = acc[f][n][3];
            }
    }
    __syncthreads();
    if (wid < 4) {
        const float* base = upbuf + wid * 2176;
#pragma unroll
        for (int f = 0; f < 2; f++)
#pragma unroll
            for (int n = 0; n < 8; n++) {
                int row = 16 * f + (lane >> 2);
                int col = 8 * n + (lane & 3) * 2;
                const float* b0 = base + row * 68 + col;
                const float* b1 = b0 + 8 * 68;
                float* o0 = g_h + (size_t)(m0 + R + row) * IDIM + n0 + col;
                float* o1 = o0 + (size_t)8 * IDIM;
                *reinterpret_cast<float2*>(o0) =
                    make_float2(silu(acc[f][n][0]) * b0[0],
                                silu(acc[f][n][1]) * b0[1]);
                *reinterpret_cast<float2*>(o1) =
                    make_float2(silu(acc[f][n][2]) * b1[0],
                                silu(acc[f][n][3]) * b1[1]);
            }
    }
}

// ---------------------------------------------------------------------------
// Kernel 2: down projection. CTA 128m x 128n, 8 warps 4m x 2n (32x64 tiles),
// 2 CTAs/SM, serial staging after MMA.
// ---------------------------------------------------------------------------
__global__ __launch_bounds__(256, 2)
void k2_down(const float* __restrict__ Wd)
{
    extern __shared__ __align__(128) char sm[];
    const uint32_t smb = smem_u32(sm);
    const int tid  = threadIdx.x;
    const int wid  = tid >> 5;
    const int lane = tid & 31;
    const int m0 = blockIdx.x * 128;
    const int n0 = blockIdx.y * 128;

    const int rbase = tid >> 3;
    const int c4    = (tid & 7) * 4;
    const float *pA[4], *pB[4];
    int sts[4];
#pragma unroll
    for (int j = 0; j < 4; j++) {
        int row = rbase + 32 * j;
        pA[j] = g_h + (size_t)(m0 + row) * IDIM + c4;
        pB[j] = Wd  + (size_t)(n0 + row) * IDIM + c4;
        sts[j] = row * ROWB + (tid & 7) * 8;
    }

    const int laneRow = ((lane >> 3) & 1) * 8 + (lane & 7);
    const int laneK   = (lane >> 4) * 16;
    const int R       = 32 * (wid & 3);
    const int Cw      = 64 * (wid >> 2);

    float acc[2][8][4];
#pragma unroll
    for (int f = 0; f < 2; f++)
#pragma unroll
        for (int n = 0; n < 8; n++)
#pragma unroll
            for (int q = 0; q < 4; q++) acc[f][n][q] = 0.f;

#define K2_STAGE(DST, K0) do {                                                 \
    char* st = (DST);                                                          \
    float4 a0 = *reinterpret_cast<const float4*>(pA[0] + (K0));                \
    float4 a1 = *reinterpret_cast<const float4*>(pA[1] + (K0));                \
    float4 a2 = *reinterpret_cast<const float4*>(pA[2] + (K0));                \
    float4 a3 = *reinterpret_cast<const float4*>(pA[3] + (K0));                \
    float4 b0 = *reinterpret_cast<const float4*>(pB[0] + (K0));                \
    float4 b1 = *reinterpret_cast<const float4*>(pB[1] + (K0));                \
    float4 b2 = *reinterpret_cast<const float4*>(pB[2] + (K0));                \
    float4 b3 = *reinterpret_cast<const float4*>(pB[3] + (K0));                \
    split_store(st + sts[0], st + K2_ALO + sts[0], a0);                        \
    split_store(st + sts[1], st + K2_ALO + sts[1], a1);                        \
    split_store(st + sts[2], st + K2_ALO + sts[2], a2);                        \
    split_store(st + sts[3], st + K2_ALO + sts[3], a3);                        \
    split_store(st + K2_BHI + sts[0], st + K2_BLO + sts[0], b0);               \
    split_store(st + K2_BHI + sts[1], st + K2_BLO + sts[1], b1);               \
    split_store(st + K2_BHI + sts[2], st + K2_BLO + sts[2], b2);               \
    split_store(st + K2_BHI + sts[3], st + K2_BLO + sts[3], b3);               \
} while (0)

    K2_STAGE(sm, 0);

#pragma unroll 1
    for (int c = 0; c < NC2; c++) {
        __syncthreads();
        const uint32_t sb = smb + (uint32_t)(c & 1) * STAGE2;
#pragma unroll
        for (int s = 0; s < 2; s++) {
            const uint32_t ab = sb + (uint32_t)((R + laneRow) * ROWB + laneK + 32 * s);
            uint32_t ah[2][4], al[2][4];
            ldsm4(ab,                      ah[0][0], ah[0][1], ah[0][2], ah[0][3]);
            ldsm4(ab + 16 * ROWB,          ah[1][0], ah[1][1], ah[1][2], ah[1][3]);
            ldsm4(ab + K2_ALO,             al[0][0], al[0][1], al[0][2], al[0][3]);
            ldsm4(ab + K2_ALO + 16 * ROWB, al[1][0], al[1][1], al[1][2], al[1][3]);
#pragma unroll
            for (int gp = 0; gp < 4; gp++) {
                const uint32_t bb = sb + (uint32_t)(K2_BHI +
                    (Cw + 16 * gp + laneRow) * ROWB + laneK + 32 * s);
                uint32_t bh[4], bl[4];
                ldsm4(bb,         bh[0], bh[1], bh[2], bh[3]);
                ldsm4(bb + 10240, bl[0], bl[1], bl[2], bl[3]);
#pragma unroll
                for (int f = 0; f < 2; f++)
#pragma unroll
                    for (int h = 0; h < 2; h++) {
                        float* cc = acc[f][2 * gp + h];
                        hmma(cc, ah[f], bh[h], bh[2 + h]);
                        hmma(cc, ah[f], bl[h], bl[2 + h]);
                        hmma(cc, al[f], bh[h], bh[2 + h]);
                    }
            }
        }
        if (c + 1 < NC2)
            K2_STAGE(sm + (size_t)((c + 1) & 1) * STAGE2, (c + 1) * 32);
    }
#undef K2_STAGE

    // epilogue: direct fp32 stores
#pragma unroll
    for (int f = 0; f < 2; f++)
#pragma unroll
        for (int n = 0; n < 8; n++) {
            int row = m0 + R + 16 * f + (lane >> 2);
            int col = n0 + Cw + 8 * n + (lane & 3) * 2;
            float* o0 = g_down + (size_t)row * HDIM + col;
            float* o1 = o0 + (size_t)8 * HDIM;
            *reinterpret_cast<float2*>(o0) = make_float2(acc[f][n][0], acc[f][n][1]);
            *reinterpret_cast<float2*>(o1) = make_float2(acc[f][n][2], acc[f][n][3]);
        }
}

// ---------------------------------------------------------------------------
// Kernel 3: scatter
// ---------------------------------------------------------------------------
__global__ __launch_bounds__(256)
void scatter_kernel(const int* __restrict__ scatter_indices,
                    float* __restrict__ out)
{
    const int t = blockIdx.x;
    const int c = scatter_indices[t];
    const float4* src = reinterpret_cast<const float4*>(g_down + (size_t)c * HDIM);
    float4*       dst = reinterpret_cast<float4*>(out + (size_t)t * HDIM);
#pragma unroll
    for (int j = threadIdx.x; j < HDIM / 4; j += 256)
        dst[j] = src[j];
}

// ---------------------------------------------------------------------------
extern "C" void kernel_launch(void* const* d_in, const int* in_sizes, int n_in,
                              void* d_out, int out_size)
{
    const float* x  = (const float*)d_in[0];
    const float* Wg = (const float*)d_in[1];
    const float* Wu = (const float*)d_in[2];
    const float* Wd = (const float*)d_in[3];
    const int*   fg = (const int*)d_in[4];
    const int*   sc = (const int*)d_in[5];
    float*       out = (float*)d_out;

    cudaFuncSetAttribute(k1_gateup, cudaFuncAttributeMaxDynamicSharedMemorySize, SMEM1);
    cudaFuncSetAttribute(k2_down,   cudaFuncAttributeMaxDynamicSharedMemorySize, SMEM2);

    dim3 g1(CDIM / 128, IDIM / 64);    // (64 m fastest, 128 n)
    k1_gateup<<<g1, 256, SMEM1>>>(x, Wg, Wu, fg);

    dim3 g2(CDIM / 128, HDIM / 128);   // (64 m fastest, 16 n)
    k2_down<<<g2, 256, SMEM2>>>(Wd);

    scatter_kernel<<<NTOK, 256>>>(sc, out);
}